// round 1
// baseline (speedup 1.0000x reference)
#include <cuda_runtime.h>

// SpikingAttentionJAX: the sequential LIF scan collapses to a per-token
// occurrence-count problem because v[t]/spikes[t] change only at steps where
// token t appears, and those updates commute across different tokens.
//
// Pipeline (4 graph-capturable kernels, no allocs, no syncs):
//   1) k_zero   : zero the count scratch (device global)
//   2) k_hist   : histogram token_seq via atomicAdd
//   3) k_gains  : per vocab entry, replay n_t LIF steps from v0[t];
//                 write gains (0.6 / 1.0); per-block top-5 of v_final
//                 (key packs value + inverted index for JAX tie-break)
//   4) k_top    : single-block merge of per-block candidates; write 1.5 at
//                 the 5 winners.

static constexpr float DECAY     = 0.7f;
static constexpr float THETA     = 1.0f;
static constexpr float GAIN_UP   = 1.5f;
static constexpr float GAIN_DOWN = 0.6f;
static constexpr int   KW        = 5;

static constexpr int MAXV      = 131072;   // >= vocab (128000), /4 aligned
static constexpr int MAXBLOCKS = 1024;

__device__ __align__(16) int g_count[MAXV];
__device__ unsigned long long g_cand[MAXBLOCKS * KW];

// ---------------------------------------------------------------- zero
__global__ void k_zero() {
    int i = blockIdx.x * blockDim.x + threadIdx.x;   // MAXV/4 threads
    reinterpret_cast<int4*>(g_count)[i] = make_int4(0, 0, 0, 0);
}

// ---------------------------------------------------------------- histogram
__global__ void k_hist(const int* __restrict__ tok, int n, int vocab) {
    int i = blockIdx.x * blockDim.x + threadIdx.x;
    if (i < n) {
        int t = tok[i];
        t = t < 0 ? 0 : (t >= vocab ? vocab - 1 : t);
        atomicAdd(&g_count[t], 1);
    }
}

// Monotonic uint mapping for float ordering (handles negatives too).
__device__ __forceinline__ unsigned ordered_bits(float f) {
    unsigned u = __float_as_uint(f);
    return (u & 0x80000000u) ? ~u : (u | 0x80000000u);
}

// ---------------------------------------------------------------- gains + per-block top-5
__global__ void k_gains(const float* __restrict__ v0,
                        float* __restrict__ out, int vocab) {
    int i = blockIdx.x * blockDim.x + threadIdx.x;
    int t = threadIdx.x;

    unsigned long long key = 0ull;
    if (i < vocab) {
        int   cnt = g_count[i];
        float v   = v0[i];
        int   s   = 0;
        for (int j = 0; j < cnt; j++) {
            float vn = DECAY * v + 1.0f;
            if (vn >= THETA) { v = vn - THETA; s++; }
            else             { v = vn; }
        }
        out[i] = (s > 0) ? GAIN_DOWN : 1.0f;
        // high value wins; on ties, LOWER index wins (JAX top_k semantics):
        key = ((unsigned long long)ordered_bits(v) << 32)
            | (unsigned long long)(0xFFFFFFFFu - (unsigned)i);
    }

    __shared__ unsigned long long sk[256];
    __shared__ unsigned long long sr[256];
    sk[t] = key;
    __syncthreads();

    for (int r = 0; r < KW; r++) {
        sr[t] = sk[t];
        __syncthreads();
        #pragma unroll
        for (int off = 128; off > 0; off >>= 1) {
            if (t < off) {
                unsigned long long o = sr[t + off];
                if (o > sr[t]) sr[t] = o;
            }
            __syncthreads();
        }
        unsigned long long best = sr[0];
        if (sk[t] == best) sk[t] = 0ull;   // keys unique (index embedded)
        if (t == 0) g_cand[blockIdx.x * KW + r] = best;
        __syncthreads();
    }
}

// ---------------------------------------------------------------- global top-5 merge
__global__ void k_top(float* __restrict__ out, int ncand) {
    int t = threadIdx.x;

    unsigned long long loc[KW + 1];        // +1 = sentinel for pointer overrun
    #pragma unroll
    for (int j = 0; j <= KW; j++) loc[j] = 0ull;

    for (int i = t; i < ncand; i += 256) {
        unsigned long long k = g_cand[i];
        if (k > loc[KW - 1]) {
            loc[KW - 1] = k;
            #pragma unroll
            for (int j = KW - 1; j > 0; j--) {
                if (loc[j] > loc[j - 1]) {
                    unsigned long long tmp = loc[j];
                    loc[j] = loc[j - 1];
                    loc[j - 1] = tmp;
                }
            }
        }
    }

    __shared__ unsigned long long sr[256];
    int p = 0;
    for (int r = 0; r < KW; r++) {
        sr[t] = loc[p];
        __syncthreads();
        #pragma unroll
        for (int off = 128; off > 0; off >>= 1) {
            if (t < off) {
                unsigned long long o = sr[t + off];
                if (o > sr[t]) sr[t] = o;
            }
            __syncthreads();
        }
        unsigned long long best = sr[0];
        __syncthreads();
        if (loc[p] == best && best != 0ull) p++;
        if (t == 0 && best != 0ull) {
            unsigned idx = 0xFFFFFFFFu - (unsigned)(best & 0xFFFFFFFFull);
            out[idx] = GAIN_UP;
        }
        __syncthreads();
    }
}

// ---------------------------------------------------------------- launch
extern "C" void kernel_launch(void* const* d_in, const int* in_sizes, int n_in,
                              void* d_out, int out_size) {
    const int*   tok = (const int*)d_in[0];
    const float* v0  = (const float*)d_in[1];
    // d_in[2] is vocab_size on device; element count of v0 gives it host-side.
    const int seq   = in_sizes[0];
    const int vocab = in_sizes[1];
    float* out = (float*)d_out;

    k_zero<<<MAXV / 4 / 256, 256>>>();
    k_hist<<<(seq + 255) / 256, 256>>>(tok, seq, vocab);

    int gblocks = (vocab + 255) / 256;           // 500 for vocab=128000
    if (gblocks > MAXBLOCKS) gblocks = MAXBLOCKS; // safety (never hit here)
    k_gains<<<gblocks, 256>>>(v0, out, vocab);
    k_top<<<1, 256>>>(out, gblocks * KW);
}

// round 2
// speedup vs baseline: 1.3400x; 1.3400x over previous
#include <cuda_runtime.h>

// SpikingAttentionJAX — single fused persistent kernel.
// The sequential LIF scan collapses to per-token occurrence counts (updates to
// distinct vocab entries commute; each entry's final state depends only on its
// count and v0). Phases inside ONE launch, separated by software grid barriers:
//   P1: histogram token_seq (atomics into g_count, which is all-zero on entry)
//   P2: per vocab entry replay count LIF steps; write gains (0.6/1.0);
//       per-block top-5 of v_final via shuffle reduction -> g_cand
//   P3: re-zero only the touched histogram bins (restores all-zero invariant
//       for the next graph replay); block 0 merges 640 candidates and writes
//       the 5 winners (1.5) with JAX tie-break (lower index wins).

static constexpr float DECAY     = 0.7f;
static constexpr float THETA     = 1.0f;
static constexpr float GAIN_UP   = 1.5f;
static constexpr float GAIN_DOWN = 0.6f;
static constexpr int   KW  = 5;
static constexpr int   NB  = 128;          // co-resident blocks (<=148 SMs)
static constexpr int   NT  = 256;
static constexpr int   MAXV = 4 * NB * NT; // 131072 >= vocab

__device__ __align__(16) int g_count[MAXV];         // zero-init; kept zero between calls
__device__ unsigned long long g_cand[NB * KW];
__device__ unsigned           g_barcnt = 0;
__device__ volatile unsigned  g_bargen = 0;          // monotonic across replays

__device__ __forceinline__ unsigned ordered_bits(float f) {
    unsigned u = __float_as_uint(f);
    return (u & 0x80000000u) ? ~u : (u | 0x80000000u);
}

__device__ __forceinline__ void grid_barrier() {
    __threadfence();           // make this thread's prior writes GPU-visible
    __syncthreads();
    if (threadIdx.x == 0) {
        unsigned gen = g_bargen;
        if (atomicAdd(&g_barcnt, 1) == (unsigned)NB - 1) {
            g_barcnt = 0;
            __threadfence();
            g_bargen = gen + 1;
        } else {
            while (g_bargen == gen) { }
        }
        __threadfence();
    }
    __syncthreads();
}

__global__ __launch_bounds__(NT, 1)
void fused_spiking(const int* __restrict__ tok, const float* __restrict__ v0,
                   float* __restrict__ out, int seq, int vocab) {
    const int tid  = threadIdx.x;
    const int lane = tid & 31;
    const int wid  = tid >> 5;
    const int g    = blockIdx.x * NT + tid;        // 0 .. NB*NT-1

    __shared__ unsigned long long swarp[NT / 32];
    __shared__ unsigned long long sbest;

    // ---- P1: histogram ----
    for (int i = g; i < seq; i += NB * NT) {
        int t = tok[i];
        t = t < 0 ? 0 : (t >= vocab ? vocab - 1 : t);
        atomicAdd(&g_count[t], 1);
    }

    grid_barrier();

    // ---- P2: gains + packed keys (4 consecutive vocab entries per thread) ----
    unsigned long long keys[4];
    #pragma unroll
    for (int j = 0; j < 4; j++) keys[j] = 0ull;

    const int base = 4 * g;
    if (base + 3 < vocab) {
        int4   c4 = __ldcg(reinterpret_cast<const int4*>(g_count) + g);
        float4 v4 = __ldg(reinterpret_cast<const float4*>(v0) + g);
        int   cnt[4] = {c4.x, c4.y, c4.z, c4.w};
        float vv[4]  = {v4.x, v4.y, v4.z, v4.w};
        float gn[4];
        #pragma unroll
        for (int j = 0; j < 4; j++) {
            float v = vv[j];
            int   s = 0;
            for (int it = 0; it < cnt[j]; it++) {
                float vn = DECAY * v + 1.0f;
                if (vn >= THETA) { v = vn - THETA; s++; }
                else             { v = vn; }
            }
            gn[j] = (s > 0) ? GAIN_DOWN : 1.0f;
            keys[j] = ((unsigned long long)ordered_bits(v) << 32)
                    | (unsigned long long)(0xFFFFFFFFu - (unsigned)(base + j));
        }
        reinterpret_cast<float4*>(out)[g] = make_float4(gn[0], gn[1], gn[2], gn[3]);
    } else if (base < vocab) {
        #pragma unroll
        for (int j = 0; j < 4; j++) {
            int i = base + j;
            if (i < vocab) {
                int   cnt = __ldcg(&g_count[i]);
                float v   = v0[i];
                int   s   = 0;
                for (int it = 0; it < cnt; it++) {
                    float vn = DECAY * v + 1.0f;
                    if (vn >= THETA) { v = vn - THETA; s++; }
                    else             { v = vn; }
                }
                out[i] = (s > 0) ? GAIN_DOWN : 1.0f;
                keys[j] = ((unsigned long long)ordered_bits(v) << 32)
                        | (unsigned long long)(0xFFFFFFFFu - (unsigned)i);
            }
        }
    }

    // ---- block top-5: 5 pop rounds, shuffle + tiny shared reduce ----
    #pragma unroll
    for (int r = 0; r < KW; r++) {
        unsigned long long m = keys[0];
        #pragma unroll
        for (int j = 1; j < 4; j++) if (keys[j] > m) m = keys[j];
        #pragma unroll
        for (int off = 16; off > 0; off >>= 1) {
            unsigned long long o = __shfl_xor_sync(0xffffffffu, m, off);
            if (o > m) m = o;
        }
        if (lane == 0) swarp[wid] = m;
        __syncthreads();
        if (tid == 0) {
            unsigned long long b = swarp[0];
            #pragma unroll
            for (int w = 1; w < NT / 32; w++) if (swarp[w] > b) b = swarp[w];
            sbest = b;
            g_cand[blockIdx.x * KW + r] = b;
        }
        __syncthreads();
        unsigned long long b = sbest;
        #pragma unroll
        for (int j = 0; j < 4; j++) if (keys[j] == b) keys[j] = 0ull;
    }

    grid_barrier();

    // ---- P3a: re-zero touched bins (restores g_count == 0 invariant) ----
    for (int i = g; i < seq; i += NB * NT) {
        int t = tok[i];
        t = t < 0 ? 0 : (t >= vocab ? vocab - 1 : t);
        g_count[t] = 0;
    }

    // ---- P3b: block 0 merges NB*KW candidates, writes winners ----
    if (blockIdx.x == 0) {
        unsigned long long mk[3];   // ceil(640/256) = 3 per thread, static index
        #pragma unroll
        for (int j = 0; j < 3; j++) {
            int i = tid + j * NT;
            mk[j] = (i < NB * KW) ? __ldcg(&g_cand[i]) : 0ull;
        }
        __syncthreads();            // swarp/sbest reuse
        #pragma unroll
        for (int r = 0; r < KW; r++) {
            unsigned long long m = mk[0];
            #pragma unroll
            for (int j = 1; j < 3; j++) if (mk[j] > m) m = mk[j];
            #pragma unroll
            for (int off = 16; off > 0; off >>= 1) {
                unsigned long long o = __shfl_xor_sync(0xffffffffu, m, off);
                if (o > m) m = o;
            }
            if (lane == 0) swarp[wid] = m;
            __syncthreads();
            if (tid == 0) {
                unsigned long long b = swarp[0];
                #pragma unroll
                for (int w = 1; w < NT / 32; w++) if (swarp[w] > b) b = swarp[w];
                sbest = b;
                if (b != 0ull) {
                    unsigned idx = 0xFFFFFFFFu - (unsigned)(b & 0xFFFFFFFFull);
                    out[idx] = GAIN_UP;
                }
            }
            __syncthreads();
            unsigned long long b = sbest;
            #pragma unroll
            for (int j = 0; j < 3; j++) if (mk[j] == b) mk[j] = 0ull;
        }
    }
}

extern "C" void kernel_launch(void* const* d_in, const int* in_sizes, int n_in,
                              void* d_out, int out_size) {
    const int*   tok = (const int*)d_in[0];
    const float* v0  = (const float*)d_in[1];
    const int seq   = in_sizes[0];
    const int vocab = in_sizes[1];
    float* out = (float*)d_out;

    fused_spiking<<<NB, NT>>>(tok, v0, out, seq, vocab);
}